// round 1
// baseline (speedup 1.0000x reference)
#include <cuda_runtime.h>

// ---------------------------------------------------------------------------
// CFConvAngular fused kernel (SchNet angular CFConv)
// B=2, A=512, T=512, F=128, n_rbf=25
// inputs (metadata order):
//  0 x[B,A,128] 1 r_ij[B,A,T,25] 2 mask[B,A,T] 3 Wf1[25,128] 4 bf1[128]
//  5 Wf2[128,128] 6 bf2[128] 7 Win[128,128] 8 Wout[128,128] 9 bout[128]
//  10 neighbors_j[B,A,T] int32  11 neighbors_k[B,A,T] int32
// output: out[B,A,128] float32
// ---------------------------------------------------------------------------

#define B_DIM 2
#define A_DIM 512
#define T_DIM 512
#define F_DIM 128
#define R_DIM 25
#define TT    64
#define NTILES (T_DIM / TT)      // 8
#define NTHREADS 256

// scratch: y = x @ Win, [B*A, F] = 512 KB (L2-resident during main kernel)
__device__ float g_y[B_DIM * A_DIM * F_DIM];

// ---------------- f32x2 packed helpers (FFMA2 path, sm_100+) ---------------
typedef unsigned long long u64t;

__device__ __forceinline__ u64t pk2(float lo, float hi) {
    u64t r; asm("mov.b64 %0, {%1,%2};" : "=l"(r) : "f"(lo), "f"(hi)); return r;
}
__device__ __forceinline__ u64t dup2(float x) { return pk2(x, x); }
__device__ __forceinline__ void up2(u64t v, float& lo, float& hi) {
    asm("mov.b64 {%0,%1}, %2;" : "=f"(lo), "=f"(hi) : "l"(v));
}
__device__ __forceinline__ u64t fma2_(u64t a, u64t b, u64t c) {
    u64t d; asm("fma.rn.f32x2 %0, %1, %2, %3;" : "=l"(d) : "l"(a), "l"(b), "l"(c)); return d;
}
__device__ __forceinline__ u64t mul2_(u64t a, u64t b) {
    u64t d; asm("mul.rn.f32x2 %0, %1, %2;" : "=l"(d) : "l"(a), "l"(b)); return d;
}
__device__ __forceinline__ u64t add2_(u64t a, u64t b) {
    u64t d; asm("add.rn.f32x2 %0, %1, %2;" : "=l"(d) : "l"(a), "l"(b)); return d;
}

// shifted softplus: softplus(v) - log(2) = max(v,0) + log(1+exp(-|v|)) - log2
__device__ __forceinline__ float sspf(float v) {
    float e = __expf(-fabsf(v));
    return fmaxf(v, 0.0f) + __logf(1.0f + e) - 0.69314718055994530942f;
}

// ------------------------- kernel 1: y = x @ Win ---------------------------
__global__ void __launch_bounds__(F_DIM) in2f_kernel(
    const float* __restrict__ x, const float* __restrict__ Win)
{
    __shared__ float sx[F_DIM];
    const int tid = threadIdx.x;
    const int blk = blockIdx.x;            // b*A + a
    sx[tid] = x[blk * F_DIM + tid];
    __syncthreads();
    float s0 = 0.f, s1 = 0.f, s2 = 0.f, s3 = 0.f;
#pragma unroll
    for (int i = 0; i < F_DIM; i += 4) {
        s0 = fmaf(sx[i + 0], Win[(i + 0) * F_DIM + tid], s0);
        s1 = fmaf(sx[i + 1], Win[(i + 1) * F_DIM + tid], s1);
        s2 = fmaf(sx[i + 2], Win[(i + 2) * F_DIM + tid], s2);
        s3 = fmaf(sx[i + 3], Win[(i + 3) * F_DIM + tid], s3);
    }
    g_y[blk * F_DIM + tid] = (s0 + s1) + (s2 + s3);
}

// --------------------- kernel 2: fused cfconv-angular ----------------------
// dyn smem layout (float offsets)
#define SWF2_OFF 0                         // 128*128 = 16384
#define SWF1_OFF 16384                     // 25*128  = 3200
#define SH1_OFF  19584                     // 64*132  = 8448  (pad 132 vs 128)
#define SR_OFF   28032                     // 64*26   = 1664  (pad 26 vs 25)
#define SJ_OFF   29696                     // 64 (int)
#define SK_OFF   29760                     // 64 (int)
#define SM_OFF   29824                     // 64
#define SFIN_OFF 29888                     // 128
#define SMEM_FLOATS 30016
#define SMEM_BYTES (SMEM_FLOATS * 4)       // 120064 B

__global__ void __launch_bounds__(NTHREADS, 1) cfconv_kernel(
    const float* __restrict__ r_ij, const float* __restrict__ mask,
    const float* __restrict__ Wf1, const float* __restrict__ bf1,
    const float* __restrict__ Wf2, const float* __restrict__ bf2,
    const float* __restrict__ Wout, const float* __restrict__ bout,
    const int* __restrict__ nj, const int* __restrict__ nk,
    float* __restrict__ out)
{
    extern __shared__ float smem[];
    float* sWf2 = smem + SWF2_OFF;
    float* sWf1 = smem + SWF1_OFF;
    float* sH1  = smem + SH1_OFF;
    float* sR   = smem + SR_OFF;
    int*   sJ   = (int*)(smem + SJ_OFF);
    int*   sK   = (int*)(smem + SK_OFF);
    float* sM   = smem + SM_OFF;
    float* sFin = smem + SFIN_OFF;

    const int tid = threadIdx.x;
    const int blk = blockIdx.x;            // b*A + a
    const int b   = blk >> 9;
    const int fg  = tid & 15;              // f-group 0..15
    const int tg  = tid >> 4;              // t-group 0..15
    const int f0  = fg * 8;
    const int t0  = tg * 4;

    // stage weights into SMEM (reused across all 8 tiles)
    for (int e = tid; e < R_DIM * F_DIM; e += NTHREADS) sWf1[e] = Wf1[e];
    for (int e = tid; e < F_DIM * F_DIM; e += NTHREADS) sWf2[e] = Wf2[e];

    // per-thread bias pairs
    u64t bf1p[4], bf2p[4];
#pragma unroll
    for (int p = 0; p < 4; p++) {
        bf1p[p] = pk2(bf1[f0 + 2 * p], bf1[f0 + 2 * p + 1]);
        bf2p[p] = pk2(bf2[f0 + 2 * p], bf2[f0 + 2 * p + 1]);
    }

    u64t acc[4];
#pragma unroll
    for (int p = 0; p < 4; p++) acc[p] = pk2(0.f, 0.f);

    const long  rbase = (long)blk * T_DIM * R_DIM;
    const int   tbase = blk * T_DIM;
    const float* ybase = g_y + (long)b * A_DIM * F_DIM;

    for (int tile = 0; tile < NTILES; ++tile) {
        // ---- stage r-tile (contiguous 1600 floats) + indices/mask ----
        {
            const long roff = rbase + (long)tile * TT * R_DIM;
            for (int e = tid; e < TT * R_DIM; e += NTHREADS) {
                sR[(e / R_DIM) * 26 + (e % R_DIM)] = r_ij[roff + e];
            }
            const int toff = tbase + tile * TT;
            if (tid < 64)                sJ[tid]       = nj[toff + tid];
            else if (tid < 128)          sK[tid - 64]  = nk[toff + tid - 64];
            else if (tid < 192)          sM[tid - 128] = mask[toff + tid - 128];
        }
        __syncthreads();

        // ---- GEMM1: H1[t][g] = ssp(sum_r R[t][r]*Wf1[r][g] + bf1[g]) ----
        {
            u64t h[4][4];
#pragma unroll
            for (int i = 0; i < 4; i++)
#pragma unroll
                for (int p = 0; p < 4; p++) h[i][p] = bf1p[p];

#pragma unroll
            for (int r = 0; r < R_DIM; r++) {
                const float4 w0 = *(const float4*)&sWf1[r * F_DIM + f0];
                const float4 w1 = *(const float4*)&sWf1[r * F_DIM + f0 + 4];
                const u64t b0 = pk2(w0.x, w0.y), b1 = pk2(w0.z, w0.w);
                const u64t b2 = pk2(w1.x, w1.y), b3 = pk2(w1.z, w1.w);
#pragma unroll
                for (int i = 0; i < 4; i++) {
                    const u64t a = dup2(sR[(t0 + i) * 26 + r]);
                    h[i][0] = fma2_(a, b0, h[i][0]);
                    h[i][1] = fma2_(a, b1, h[i][1]);
                    h[i][2] = fma2_(a, b2, h[i][2]);
                    h[i][3] = fma2_(a, b3, h[i][3]);
                }
            }
            // ssp + store H1 tile
#pragma unroll
            for (int i = 0; i < 4; i++) {
                float v[8];
#pragma unroll
                for (int p = 0; p < 4; p++) up2(h[i][p], v[2 * p], v[2 * p + 1]);
                float o[8];
#pragma unroll
                for (int e = 0; e < 8; e++) o[e] = sspf(v[e]);
                *(float4*)&sH1[(t0 + i) * 132 + f0]     = make_float4(o[0], o[1], o[2], o[3]);
                *(float4*)&sH1[(t0 + i) * 132 + f0 + 4] = make_float4(o[4], o[5], o[6], o[7]);
            }
        }
        __syncthreads();

        // ---- GEMM2: W[t][f] = sum_k H1[t][k]*Wf2[k][f]  (kept in regs) ----
        u64t pw[4][4];
#pragma unroll
        for (int i = 0; i < 4; i++)
#pragma unroll
            for (int p = 0; p < 4; p++) pw[i][p] = pk2(0.f, 0.f);

#pragma unroll 8
        for (int k = 0; k < F_DIM; k++) {
            const float4 w0 = *(const float4*)&sWf2[k * F_DIM + f0];
            const float4 w1 = *(const float4*)&sWf2[k * F_DIM + f0 + 4];
            const u64t b0 = pk2(w0.x, w0.y), b1 = pk2(w0.z, w0.w);
            const u64t b2 = pk2(w1.x, w1.y), b3 = pk2(w1.z, w1.w);
#pragma unroll
            for (int i = 0; i < 4; i++) {
                const u64t a = dup2(sH1[(t0 + i) * 132 + k]);
                pw[i][0] = fma2_(a, b0, pw[i][0]);
                pw[i][1] = fma2_(a, b1, pw[i][1]);
                pw[i][2] = fma2_(a, b2, pw[i][2]);
                pw[i][3] = fma2_(a, b3, pw[i][3]);
            }
        }

        // ---- epilogue: acc[f] += (W+bf2) * y_j * y_k * mask ----
#pragma unroll
        for (int i = 0; i < 4; i++) {
            const int t  = t0 + i;
            const int jj = sJ[t];
            const int kk = sK[t];
            const float m = sM[t];
            const float4* yj = (const float4*)&ybase[jj * F_DIM + f0];
            const float4* yk = (const float4*)&ybase[kk * F_DIM + f0];
            const float4 aj0 = yj[0], aj1 = yj[1];
            const float4 ak0 = yk[0], ak1 = yk[1];
            const u64t zj[4] = { pk2(aj0.x, aj0.y), pk2(aj0.z, aj0.w),
                                 pk2(aj1.x, aj1.y), pk2(aj1.z, aj1.w) };
            const u64t zk[4] = { pk2(ak0.x, ak0.y), pk2(ak0.z, ak0.w),
                                 pk2(ak1.x, ak1.y), pk2(ak1.z, ak1.w) };
            const u64t md = dup2(m);
#pragma unroll
            for (int p = 0; p < 4; p++) {
                const u64t w = add2_(pw[i][p], bf2p[p]);
                const u64t z = mul2_(mul2_(zj[p], zk[p]), md);
                acc[p] = fma2_(w, z, acc[p]);
            }
        }
        __syncthreads();   // protect sR/sH1 for next tile
    }

    // ---- cross-t-group reduction (reuse sH1 as [16][128]) ----
    float* sRed = sH1;
#pragma unroll
    for (int p = 0; p < 4; p++) {
        float lo, hi;
        up2(acc[p], lo, hi);
        sRed[tg * F_DIM + f0 + 2 * p]     = lo;
        sRed[tg * F_DIM + f0 + 2 * p + 1] = hi;
    }
    __syncthreads();

    if (tid < F_DIM) {
        float s = 0.f;
#pragma unroll
        for (int g = 0; g < 16; g++) s += sRed[g * F_DIM + tid];
        sFin[tid] = s;
    }
    __syncthreads();

    // ---- f2out: out[o] = ssp(sum_f acc[f]*Wout[f][o] + bout[o]) ----
    if (tid < F_DIM) {
        float s0 = 0.f, s1 = 0.f, s2 = 0.f, s3 = 0.f;
#pragma unroll
        for (int f = 0; f < F_DIM; f += 4) {
            s0 = fmaf(sFin[f + 0], Wout[(f + 0) * F_DIM + tid], s0);
            s1 = fmaf(sFin[f + 1], Wout[(f + 1) * F_DIM + tid], s1);
            s2 = fmaf(sFin[f + 2], Wout[(f + 2) * F_DIM + tid], s2);
            s3 = fmaf(sFin[f + 3], Wout[(f + 3) * F_DIM + tid], s3);
        }
        const float v = (s0 + s1) + (s2 + s3) + bout[tid];
        out[blk * F_DIM + tid] = sspf(v);
    }
}

// ------------------------------- launcher ----------------------------------
extern "C" void kernel_launch(void* const* d_in, const int* in_sizes, int n_in,
                              void* d_out, int out_size)
{
    const float* x    = (const float*)d_in[0];
    const float* r_ij = (const float*)d_in[1];
    const float* mask = (const float*)d_in[2];
    const float* Wf1  = (const float*)d_in[3];
    const float* bf1  = (const float*)d_in[4];
    const float* Wf2  = (const float*)d_in[5];
    const float* bf2  = (const float*)d_in[6];
    const float* Win  = (const float*)d_in[7];
    const float* Wout = (const float*)d_in[8];
    const float* bout = (const float*)d_in[9];
    const int*   nj   = (const int*)d_in[10];
    const int*   nk   = (const int*)d_in[11];
    float* out = (float*)d_out;

    cudaFuncSetAttribute(cfconv_kernel,
                         cudaFuncAttributeMaxDynamicSharedMemorySize, SMEM_BYTES);

    in2f_kernel<<<B_DIM * A_DIM, F_DIM>>>(x, Win);
    cfconv_kernel<<<B_DIM * A_DIM, NTHREADS, SMEM_BYTES>>>(
        r_ij, mask, Wf1, bf1, Wf2, bf2, Wout, bout, nj, nk, out);
}

// round 3
// speedup vs baseline: 1.9628x; 1.9628x over previous
#include <cuda_runtime.h>
#include <cuda_fp16.h>
#include <cstdint>

// ---------------------------------------------------------------------------
// CFConvAngular: warp-MMA (mma.sync m16n8k16 f16) version — no 'a'-features.
// B=2, A=512, T=512, F=128, n_rbf=25. One CTA per (b,a). T tiled by 128.
// Per tile:  H1 = ssp(r@Wf1+bf1)            (FFMA2 fp32 -> fp16 SMEM)
//            D^T[f][t] = Wf2^T @ H1^T       (mma.sync, A frags in regs)
//            acc[f] += (D+bf2[f]) * y[j(t)][f]*y[k(t)][f]*m[t]
// Final:     out = ssp(acc @ Wout + bout)
// ---------------------------------------------------------------------------

#define B_DIM 2
#define A_DIM 512
#define T_DIM 512
#define F_DIM 128
#define R_DIM 25
#define TT    128
#define NTILES (T_DIM / TT)     // 4
#define NT    256               // 8 warps

__device__ float g_y[B_DIM * A_DIM * F_DIM];

// ---------------- f32x2 helpers (GEMM1) ----------------
typedef unsigned long long u64t;
__device__ __forceinline__ u64t pk2(float lo, float hi) {
    u64t r; asm("mov.b64 %0, {%1,%2};" : "=l"(r) : "f"(lo), "f"(hi)); return r;
}
__device__ __forceinline__ u64t dup2(float x) { return pk2(x, x); }
__device__ __forceinline__ void up2(u64t v, float& lo, float& hi) {
    asm("mov.b64 {%0,%1}, %2;" : "=f"(lo), "=f"(hi) : "l"(v));
}
__device__ __forceinline__ u64t fma2_(u64t a, u64t b, u64t c) {
    u64t d; asm("fma.rn.f32x2 %0, %1, %2, %3;" : "=l"(d) : "l"(a), "l"(b), "l"(c)); return d;
}

// shifted softplus
__device__ __forceinline__ float sspf(float v) {
    float e = __expf(-fabsf(v));
    return fmaxf(v, 0.0f) + __logf(1.0f + e) - 0.69314718055994530942f;
}

// mma.sync m16n8k16 row.col f32 = f16 * f16 + f32
__device__ __forceinline__ void mma16816(float& c0, float& c1, float& c2, float& c3,
                                         uint32_t a0, uint32_t a1, uint32_t a2, uint32_t a3,
                                         uint32_t b0, uint32_t b1) {
    asm volatile("mma.sync.aligned.m16n8k16.row.col.f32.f16.f16.f32 "
                 "{%0,%1,%2,%3}, {%4,%5,%6,%7}, {%8,%9}, {%0,%1,%2,%3};"
                 : "+f"(c0), "+f"(c1), "+f"(c2), "+f"(c3)
                 : "r"(a0), "r"(a1), "r"(a2), "r"(a3), "r"(b0), "r"(b1));
}

// ------------------------- kernel 1: y = x @ Win ---------------------------
__global__ void __launch_bounds__(F_DIM) in2f_kernel(
    const float* __restrict__ x, const float* __restrict__ Win)
{
    __shared__ float sx[F_DIM];
    const int tid = threadIdx.x;
    const int blk = blockIdx.x;
    sx[tid] = x[blk * F_DIM + tid];
    __syncthreads();
    float s0 = 0.f, s1 = 0.f, s2 = 0.f, s3 = 0.f;
#pragma unroll
    for (int i = 0; i < F_DIM; i += 4) {
        s0 = fmaf(sx[i + 0], Win[(i + 0) * F_DIM + tid], s0);
        s1 = fmaf(sx[i + 1], Win[(i + 1) * F_DIM + tid], s1);
        s2 = fmaf(sx[i + 2], Win[(i + 2) * F_DIM + tid], s2);
        s3 = fmaf(sx[i + 3], Win[(i + 3) * F_DIM + tid], s3);
    }
    g_y[blk * F_DIM + tid] = (s0 + s1) + (s2 + s3);
}

// ------------------------- main fused kernel -------------------------------
// SMEM byte layout. H1 rows: 136 halves (272B) padded -> conflict-light.
#define H1_STRIDE_B 272
#define OFF_H1   0                        // 128*272 = 34816
#define OFF_WF1  34816                    // 25*128 f32 = 12800
#define OFF_R    47616                    // 128*26 f32 = 13312
#define OFF_J    60928                    // 128 int
#define OFF_K    61440                    // 128 int
#define OFF_M    61952                    // 128 f32
#define OFF_ACC  62464                    // 128 f32
#define SMEM_BYTES 62976

__global__ void __launch_bounds__(NT, 1) cfconv_kernel(
    const float* __restrict__ r_ij, const float* __restrict__ mask,
    const float* __restrict__ Wf1, const float* __restrict__ bf1,
    const float* __restrict__ Wf2, const float* __restrict__ bf2,
    const float* __restrict__ Wout, const float* __restrict__ bout,
    const int* __restrict__ nj, const int* __restrict__ nk,
    float* __restrict__ out)
{
    extern __shared__ char smem[];
    const int tid = threadIdx.x;
    const int wid = tid >> 5;
    const int lane = tid & 31;
    const int g   = lane >> 2;            // 0..7
    const int tig = lane & 3;             // 0..3
    const int blk = blockIdx.x;
    const int b   = blk >> 9;

    float* sWf1 = (float*)(smem + OFF_WF1);
    float* sR   = (float*)(smem + OFF_R);
    int*   sJ   = (int*)(smem + OFF_J);
    int*   sK   = (int*)(smem + OFF_K);
    float* sM   = (float*)(smem + OFF_M);
    float* sAcc = (float*)(smem + OFF_ACC);

    // ---- stage Wf1 (fp32) ----
    for (int e = tid; e < R_DIM * F_DIM; e += NT) sWf1[e] = Wf1[e];

    // ---- load loop-invariant A fragments: A = Wf2^T [f][k], row-major ----
    // warp owns f rows [wid*16, wid*16+16)
    const int fw   = wid * 16;
    const int f_lo = fw + g;
    const int f_hi = fw + g + 8;
    uint32_t aA[8][4];
#pragma unroll
    for (int ks = 0; ks < 8; ks++) {
        const int k0 = ks * 16 + tig * 2;
        __half2 h;
        h = __floats2half2_rn(Wf2[k0 * F_DIM + f_lo], Wf2[(k0 + 1) * F_DIM + f_lo]);
        aA[ks][0] = *(uint32_t*)&h;
        h = __floats2half2_rn(Wf2[k0 * F_DIM + f_hi], Wf2[(k0 + 1) * F_DIM + f_hi]);
        aA[ks][1] = *(uint32_t*)&h;
        h = __floats2half2_rn(Wf2[(k0 + 8) * F_DIM + f_lo], Wf2[(k0 + 9) * F_DIM + f_lo]);
        aA[ks][2] = *(uint32_t*)&h;
        h = __floats2half2_rn(Wf2[(k0 + 8) * F_DIM + f_hi], Wf2[(k0 + 9) * F_DIM + f_hi]);
        aA[ks][3] = *(uint32_t*)&h;
    }
    const float bf2_lo = bf2[f_lo];
    const float bf2_hi = bf2[f_hi];

    // ---- GEMM1 thread mapping: kg = k-block of 16, tq*4+i = t rows ----
    const int kg = tid & 7;
    const int tq = tid >> 3;
    u64t bf1p[8];
#pragma unroll
    for (int p = 0; p < 8; p++)
        bf1p[p] = pk2(bf1[kg * 16 + 2 * p], bf1[kg * 16 + 2 * p + 1]);

    const long   rbase = (long)blk * T_DIM * R_DIM;
    const int    tbase = blk * T_DIM;
    const float* ybase = g_y + (long)b * A_DIM * F_DIM;

    float acc_lo = 0.f, acc_hi = 0.f;

    for (int tile = 0; tile < NTILES; ++tile) {
        // ---- stage r tile + indices ----
        {
            const long roff = rbase + (long)tile * TT * R_DIM;
            for (int e = tid; e < TT * R_DIM; e += NT)
                sR[(e / R_DIM) * 26 + (e % R_DIM)] = r_ij[roff + e];
            const int toff = tbase + tile * TT;
            if (tid < TT) {
                sJ[tid] = nj[toff + tid];
                sK[tid] = nk[toff + tid];
                sM[tid] = mask[toff + tid];
            }
        }
        __syncthreads();

        // ---- GEMM1: H1[t][k] = ssp(r@Wf1+bf1), 4 t-rows x 16 k per thread ----
        {
            u64t h[4][8];
#pragma unroll
            for (int i = 0; i < 4; i++)
#pragma unroll
                for (int p = 0; p < 8; p++) h[i][p] = bf1p[p];

#pragma unroll 5
            for (int r = 0; r < R_DIM; r++) {
                const float* wrow = &sWf1[r * F_DIM + kg * 16];
                const float4 w0 = *(const float4*)(wrow + 0);
                const float4 w1 = *(const float4*)(wrow + 4);
                const float4 w2 = *(const float4*)(wrow + 8);
                const float4 w3 = *(const float4*)(wrow + 12);
                const u64t wb[8] = { pk2(w0.x, w0.y), pk2(w0.z, w0.w),
                                     pk2(w1.x, w1.y), pk2(w1.z, w1.w),
                                     pk2(w2.x, w2.y), pk2(w2.z, w2.w),
                                     pk2(w3.x, w3.y), pk2(w3.z, w3.w) };
#pragma unroll
                for (int i = 0; i < 4; i++) {
                    const u64t a = dup2(sR[(tq * 4 + i) * 26 + r]);
#pragma unroll
                    for (int p = 0; p < 8; p++) h[i][p] = fma2_(a, wb[p], h[i][p]);
                }
            }
            // ssp -> fp16 -> SMEM
#pragma unroll
            for (int i = 0; i < 4; i++) {
                const int t = tq * 4 + i;
                uint32_t u[8];
#pragma unroll
                for (int p = 0; p < 8; p++) {
                    float lo, hi; up2(h[i][p], lo, hi);
                    __half2 hh = __floats2half2_rn(sspf(lo), sspf(hi));
                    u[p] = *(uint32_t*)&hh;
                }
                char* dst = smem + OFF_H1 + t * H1_STRIDE_B + kg * 32;
                *(uint4*)(dst)      = make_uint4(u[0], u[1], u[2], u[3]);
                *(uint4*)(dst + 16) = make_uint4(u[4], u[5], u[6], u[7]);
            }
        }
        __syncthreads();

        // ---- MMA + epilogue, per 8-t block ----
#pragma unroll 4
        for (int nb = 0; nb < 16; nb++) {
            // B frags: col n = g -> t = nb*8+g ; b0/b1 from H1 row (half2 words)
            const uint32_t* brow =
                (const uint32_t*)(smem + OFF_H1 + (nb * 8 + g) * H1_STRIDE_B);
            float c0 = 0.f, c1 = 0.f, c2 = 0.f, c3 = 0.f;
#pragma unroll
            for (int ks = 0; ks < 8; ks++) {
                const uint32_t b0 = brow[ks * 8 + tig];
                const uint32_t b1 = brow[ks * 8 + tig + 4];
                mma16816(c0, c1, c2, c3,
                         aA[ks][0], aA[ks][1], aA[ks][2], aA[ks][3], b0, b1);
            }
            // epilogue: this thread holds D^T[f_lo/f_hi][t_a/t_b]
            const int t_a = nb * 8 + tig * 2;
            const int t_b = t_a + 1;
            const int ja = sJ[t_a], ka = sK[t_a];
            const int jb = sJ[t_b], kb = sK[t_b];
            const float ma = sM[t_a], mb = sM[t_b];
            const float* yja = ybase + ja * F_DIM;
            const float* yka = ybase + ka * F_DIM;
            const float* yjb = ybase + jb * F_DIM;
            const float* ykb = ybase + kb * F_DIM;
            const float za_lo = yja[f_lo] * yka[f_lo] * ma;
            const float za_hi = yja[f_hi] * yka[f_hi] * ma;
            const float zb_lo = yjb[f_lo] * ykb[f_lo] * mb;
            const float zb_hi = yjb[f_hi] * ykb[f_hi] * mb;
            acc_lo = fmaf(c0 + bf2_lo, za_lo, acc_lo);
            acc_lo = fmaf(c1 + bf2_lo, zb_lo, acc_lo);
            acc_hi = fmaf(c2 + bf2_hi, za_hi, acc_hi);
            acc_hi = fmaf(c3 + bf2_hi, zb_hi, acc_hi);
        }
        __syncthreads();   // protect H1/sR/sJ for next tile
    }

    // ---- reduce over tig (quad) and publish acc[f] ----
    acc_lo += __shfl_xor_sync(0xFFFFFFFF, acc_lo, 1);
    acc_lo += __shfl_xor_sync(0xFFFFFFFF, acc_lo, 2);
    acc_hi += __shfl_xor_sync(0xFFFFFFFF, acc_hi, 1);
    acc_hi += __shfl_xor_sync(0xFFFFFFFF, acc_hi, 2);
    if (tig == 0) {
        sAcc[f_lo] = acc_lo;
        sAcc[f_hi] = acc_hi;
    }
    __syncthreads();

    // ---- f2out ----
    if (tid < F_DIM) {
        float s0 = 0.f, s1 = 0.f, s2 = 0.f, s3 = 0.f;
#pragma unroll
        for (int f = 0; f < F_DIM; f += 4) {
            s0 = fmaf(sAcc[f + 0], Wout[(f + 0) * F_DIM + tid], s0);
            s1 = fmaf(sAcc[f + 1], Wout[(f + 1) * F_DIM + tid], s1);
            s2 = fmaf(sAcc[f + 2], Wout[(f + 2) * F_DIM + tid], s2);
            s3 = fmaf(sAcc[f + 3], Wout[(f + 3) * F_DIM + tid], s3);
        }
        out[blk * F_DIM + tid] = sspf((s0 + s1) + (s2 + s3) + bout[tid]);
    }
}

// ------------------------------- launcher ----------------------------------
extern "C" void kernel_launch(void* const* d_in, const int* in_sizes, int n_in,
                              void* d_out, int out_size)
{
    const float* x    = (const float*)d_in[0];
    const float* r_ij = (const float*)d_in[1];
    const float* mask = (const float*)d_in[2];
    const float* Wf1  = (const float*)d_in[3];
    const float* bf1  = (const float*)d_in[4];
    const float* Wf2  = (const float*)d_in[5];
    const float* bf2  = (const float*)d_in[6];
    const float* Win  = (const float*)d_in[7];
    const float* Wout = (const float*)d_in[8];
    const float* bout = (const float*)d_in[9];
    const int*   nj   = (const int*)d_in[10];
    const int*   nk   = (const int*)d_in[11];
    float* out = (float*)d_out;

    cudaFuncSetAttribute(cfconv_kernel,
                         cudaFuncAttributeMaxDynamicSharedMemorySize, SMEM_BYTES);

    in2f_kernel<<<B_DIM * A_DIM, F_DIM>>>(x, Win);
    cfconv_kernel<<<B_DIM * A_DIM, NT, SMEM_BYTES>>>(
        r_ij, mask, Wf1, bf1, Wf2, bf2, Wout, bout, nj, nk, out);
}